// round 10
// baseline (speedup 1.0000x reference)
#include <cuda_runtime.h>

#define HH 1024
#define WW 1024
#define NPTS 128
#define NB 128            // row-blocks: 8 rows each
#define WPR 32            // 32-bit words per row
#define SENTINEL_D 2048   // > max 1D distance (1023); squares stay exact in int/f32

// Per-(rowblock, point) partial mins. Layout [b][n] so finalize reads coalesced.
__device__ int g_part_on [NB * NPTS];
__device__ int g_part_off[NB * NPTS];

// Nearest set-bit distance from query col q (= wc0*32+bit0) to set bits of
// word m at word index w. Sentinel if empty. (Proven in rounds 3/5/6.)
__device__ __forceinline__ int nearest_in_word(unsigned int m, int w, int wc0, int bit0) {
    if (m == 0u) return SENTINEL_D;
    if (w == wc0) {
        unsigned int maskLE = (bit0 == 31) ? 0xFFFFFFFFu : ((2u << bit0) - 1u);
        unsigned int lo = m & maskLE;
        unsigned int hi = m & ~maskLE;
        int d = SENTINEL_D;
        if (lo) d = bit0 - (31 - __clz(lo));
        if (hi) { int d2 = (__ffs(hi) - 1) - bit0; d = min(d, d2); }
        return d;
    } else if (w > wc0) {
        return (w << 5) + (__ffs(m) - 1) - ((wc0 << 5) + bit0);
    } else {
        return ((wc0 << 5) + bit0) - ((w << 5) + (31 - __clz(m)));
    }
}

// ---------------------------------------------------------------------------
// Kernel 1: fused bitpack + row-search. Block b owns rows [8b, 8b+8).
//  Phase A: pack 8 rows (8192 floats, 2 float4/thread, fully coalesced DRAM)
//           into shared bit-words (stride 33 to kill bank conflicts).
//  Phase B: thread t -> point n = t>>3, local row rl = t&7. Ring search over
//           SMEM words for nearest on/off col; combine with (r-pr)^2; subwarp
//           min over the 8 rows; stage; coalesced store of partials.
// No atomics, no fences, no cross-block anything.
// ---------------------------------------------------------------------------
__global__ void __launch_bounds__(1024, 1)
pack_search_kernel(const float* __restrict__ hd,
                   const int*   __restrict__ pred) {
    int b   = blockIdx.x;
    int tid = threadIdx.x;

    __shared__ unsigned int s_bits[8 * 33];   // [rl*33 + w]
    __shared__ int   s_pred[2 * NPTS];
    __shared__ int   s_on [NPTS];
    __shared__ int   s_off[NPTS];

    if (tid < 2 * NPTS) s_pred[tid] = pred[tid];

    // ---- Phase A: bitpack 8 rows into smem ----
    const float4* slab = reinterpret_cast<const float4*>(hd + (size_t)b * 8 * WW);
    #pragma unroll
    for (int i = 0; i < 2; i++) {
        int f = tid + i * 1024;            // float4 index within the 8-row slab
        float4 v = slab[f];
        unsigned int nib = (v.x != 0.0f ? 1u : 0u)
                         | (v.y != 0.0f ? 2u : 0u)
                         | (v.z != 0.0f ? 4u : 0u)
                         | (v.w != 0.0f ? 8u : 0u);
        unsigned int wv = nib << ((f & 7) * 4);
        wv |= __shfl_xor_sync(0xFFFFFFFFu, wv, 1);
        wv |= __shfl_xor_sync(0xFFFFFFFFu, wv, 2);
        wv |= __shfl_xor_sync(0xFFFFFFFFu, wv, 4);
        if ((f & 7) == 0) {
            int rl = f >> 8;               // 256 float4 per row
            int w  = (f & 255) >> 3;       // 8 float4 per 32-col word
            s_bits[rl * 33 + w] = wv;
        }
    }
    __syncthreads();

    // ---- Phase B: per-(point, row) ring search on smem ----
    int n  = tid >> 3;
    int rl = tid & 7;
    int r  = (b << 3) + rl;
    int pr = s_pred[2 * n];
    int pc = s_pred[2 * n + 1];

    int wc0  = pc >> 5;
    int bit0 = pc & 31;
    int q32  = (wc0 << 5) + bit0;
    const unsigned int* row = &s_bits[rl * 33];

    unsigned int m0 = row[wc0];
    int don  = nearest_in_word(m0,  wc0, wc0, bit0);
    int doff = nearest_in_word(~m0, wc0, wc0, bit0);
    if (wc0 - 1 >= 0) {
        unsigned int mL = row[wc0 - 1];
        don  = min(don,  nearest_in_word(mL,  wc0 - 1, wc0, bit0));
        doff = min(doff, nearest_in_word(~mL, wc0 - 1, wc0, bit0));
    }
    if (wc0 + 1 < WPR) {
        unsigned int mR = row[wc0 + 1];
        don  = min(don,  nearest_in_word(mR,  wc0 + 1, wc0, bit0));
        doff = min(doff, nearest_in_word(~mR, wc0 + 1, wc0, bit0));
    }
    {   // rare extension beyond ring 1 (all smem)
        int cminR = (wc0 + 2 < WPR) ? ((wc0 + 2) << 5) - q32        : SENTINEL_D;
        int cminL = (wc0 - 2 >= 0)  ? q32 - (((wc0 - 2) << 5) + 31) : SENTINEL_D;
        int nextmin = min(cminR, cminL);
        if (don > nextmin || doff > nextmin) {
            #pragma unroll 1
            for (int k = 2; k <= WPR; k++) {
                int wr = wc0 + k, wl = wc0 - k;
                if (wr < WPR) {
                    unsigned int m = row[wr];
                    don  = min(don,  nearest_in_word(m,  wr, wc0, bit0));
                    doff = min(doff, nearest_in_word(~m, wr, wc0, bit0));
                }
                if (wl >= 0) {
                    unsigned int m = row[wl];
                    don  = min(don,  nearest_in_word(m,  wl, wc0, bit0));
                    doff = min(doff, nearest_in_word(~m, wl, wc0, bit0));
                }
                int cR = (wr + 1 < WPR) ? ((wr + 1) << 5) - q32        : SENTINEL_D;
                int cL = (wl - 1 >= 0)  ? q32 - (((wl - 1) << 5) + 31) : SENTINEL_D;
                int nm = min(cR, cL);
                if (don <= nm && doff <= nm) break;
            }
        }
    }

    int dr  = r - pr;
    int dr2 = dr * dr;
    int von  = dr2 + don * don;          // < 2^23, exact in int and f32
    int voff = dr2 + doff * doff;

    // min over the 8 rows of this point (threads 8n..8n+7, group-aligned in warp)
    #pragma unroll
    for (int o = 4; o > 0; o >>= 1) {
        von  = min(von,  __shfl_xor_sync(0xFFFFFFFFu, von,  o));
        voff = min(voff, __shfl_xor_sync(0xFFFFFFFFu, voff, o));
    }
    if (rl == 0) { s_on[n] = von; s_off[n] = voff; }
    __syncthreads();

    if (tid < NPTS) {                    // coalesced 512B stores
        g_part_on [b * NPTS + tid] = s_on[tid];
        g_part_off[b * NPTS + tid] = s_off[tid];
    }
}

// ---------------------------------------------------------------------------
// Kernel 2: reduce partials over row-blocks + per-point loss + mean.
// 1024 threads: thread = (chunk c = tid>>7, point n = tid&127); each min-
// reduces 16 row-blocks (independent coalesced loads, MLP=32), smem tree over
// chunks, then first 128 threads do the loss and a sum reduce.
// ---------------------------------------------------------------------------
__global__ void __launch_bounds__(1024, 1)
finalize_kernel(const float* __restrict__ hd,
                const int*   __restrict__ pred,
                float*       __restrict__ out) {
    int tid = threadIdx.x;
    int n   = tid & 127;
    int c   = tid >> 7;      // 8 chunks of 16 row-blocks

    int von = 0x7F000000, voff = 0x7F000000;
    #pragma unroll
    for (int j = 0; j < 16; j++) {
        int b = c * 16 + j;
        von  = min(von,  g_part_on [b * NPTS + n]);
        voff = min(voff, g_part_off[b * NPTS + n]);
    }

    __shared__ int s_on[1024];
    __shared__ int s_off[1024];
    s_on[tid] = von; s_off[tid] = voff;
    __syncthreads();
    #pragma unroll
    for (int st = 512; st >= 128; st >>= 1) {
        if (tid < st) {
            s_on[tid]  = min(s_on[tid],  s_on[tid + st]);
            s_off[tid] = min(s_off[tid], s_off[tid + st]);
        }
        __syncthreads();
    }

    __shared__ float s_sum[NPTS];
    if (tid < NPTS) {
        int px = pred[2 * tid];
        int py = pred[2 * tid + 1];
        bool outside_frame = (px < 0) || (px > HH) || (py < 0) || (py > WW);
        float loss = 0.0f;
        if (!outside_frame) {
            // Reference's swapped-index neighbor lookup, JAX-clamped:
            // hd_map[py-1..py, px-1..px] with px=pred[:,0], py=pred[:,1].
            int r0 = min(max(py - 1, 0), HH - 1);
            int r1 = min(max(py,     0), HH - 1);
            int c0 = min(max(px - 1, 0), WW - 1);
            int c1 = min(max(px,     0), WW - 1);
            bool road = (hd[r0 * WW + c0] == 1.0f) || (hd[r0 * WW + c1] == 1.0f) ||
                        (hd[r1 * WW + c0] == 1.0f) || (hd[r1 * WW + c1] == 1.0f);
            const float K1 = 21.7f;
            const float LN2_OVER_K2 = 0.69314718055994531f / 40.0f;
            loss = road ? expf(sqrtf((float)s_off[tid]) * LN2_OVER_K2)
                        : expf(-(float)s_on[tid] / K1);
        }
        s_sum[tid] = loss;
    }
    __syncthreads();
    if (tid < 64) s_sum[tid] += s_sum[tid + 64];
    __syncthreads();
    if (tid < 32) {
        float v = s_sum[tid] + s_sum[tid + 32];
        #pragma unroll
        for (int o = 16; o > 0; o >>= 1)
            v += __shfl_xor_sync(0xFFFFFFFFu, v, o);
        if (tid == 0) out[0] = v * (1.0f / (float)NPTS);
    }
}

extern "C" void kernel_launch(void* const* d_in, const int* in_sizes, int n_in,
                              void* d_out, int out_size) {
    const float* hd  = (const float*)d_in[0];
    const int* pred  = (const int*)d_in[1];
    float* out       = (float*)d_out;

    pack_search_kernel<<<NB, 1024>>>(hd, pred);
    finalize_kernel<<<1, 1024>>>(hd, pred, out);
}

// round 11
// speedup vs baseline: 1.2294x; 1.2294x over previous
#include <cuda_runtime.h>

#define HH 1024
#define WW 1024
#define NPTS 128
#define BIGD 16384        // sentinel 1D distance; BIGD^2 = 2.7e8 fits int

// Single launch, single block, zero cross-block anything.
// 1024 threads = 128 points x 8 row-slots. Each point's 8-thread group scans
// row batches expanding outward from pr; per row, nearest on/off column found
// by an aligned float4 window around pc with lazy extension. Both ring loops
// carry exact lower-bound certificates, so the result equals the full 2D min.
__global__ void __launch_bounds__(1024, 1)
roadloss_kernel(const float* __restrict__ hd,
                const int*   __restrict__ pred,
                float*       __restrict__ out) {
    int tid  = threadIdx.x;
    int n    = tid >> 3;          // point index 0..127
    int rl   = tid & 7;           // row-slot within point group
    bool up  = (rl < 4);

    int pr = pred[2 * n];         // component 0: compared against rows in d2
    int pc = pred[2 * n + 1];     // component 1: compared against cols in d2

    // Prefetch loss-neighbor values early (tid<128: one point each).
    // Reference indexes hd_map[py-1..py, px-1..px] with px=pred[:,0],
    // py=pred[:,1] (roles swapped vs the distance computation), JAX-clamped.
    float nv0 = 0.f, nv1 = 0.f, nv2 = 0.f, nv3 = 0.f;
    if (tid < NPTS) {
        int px = pred[2 * tid];
        int py = pred[2 * tid + 1];
        int r0 = min(max(py - 1, 0), HH - 1);
        int r1 = min(max(py,     0), HH - 1);
        int c0 = min(max(px - 1, 0), WW - 1);
        int c1 = min(max(px,     0), WW - 1);
        nv0 = hd[r0 * WW + c0];
        nv1 = hd[r0 * WW + c1];
        nv2 = hd[r1 * WW + c0];
        nv3 = hd[r1 * WW + c1];
    }

    // 8-lane group mask for shfl reductions (groups are lane-aligned).
    unsigned int gmask = 0xFFu << ((tid & 31) & ~7);

    int best_on  = 0x3FFFFFFF;
    int best_off = 0x3FFFFFFF;

    // Row-ring batches: batch j covers offsets {4j..4j+3} (up lanes) and
    // {-(4j+1)..-(4j+4)} (down lanes) -> full row coverage as j grows.
    #pragma unroll 1
    for (int j = 0; j < 256; j++) {
        int off = up ? (4 * j + rl) : -(4 * j + (rl - 3));
        int r   = pr + off;

        int von = 0x3FFFFFFF, voff = 0x3FFFFFFF;
        if (r >= 0 && r < HH) {
            const float4* rowp = reinterpret_cast<const float4*>(hd + r * WW);

            // Aligned 8-col window containing pc.
            int c0 = (pc - 4) & ~3;
            if (c0 < 0) c0 = 0;
            if (c0 > WW - 8) c0 = WW - 8;
            float4 a = rowp[(c0 >> 2)];
            float4 b = rowp[(c0 >> 2) + 1];

            int don = BIGD, doff = BIGD;
            {
                float w[8] = {a.x, a.y, a.z, a.w, b.x, b.y, b.z, b.w};
                #pragma unroll
                for (int t = 0; t < 8; t++) {
                    int d = abs(c0 + t - pc);
                    if (w[t] != 0.0f) don = min(don, d); else doff = min(doff, d);
                }
            }
            // Lazy column extension; L == 3 (mod 4), R == 0 (mod 4).
            int L = c0 - 1;
            int R = c0 + 8;
            #pragma unroll 1
            while (true) {
                int bl = (L >= 0) ? (pc - L) : 0x3FFFFFFF;
                int br = (R < WW) ? (R - pc) : 0x3FFFFFFF;
                int bound = min(bl, br);
                if (don <= bound && doff <= bound) break;
                if (bl <= br) {
                    float4 v = rowp[(L - 3) >> 2];
                    float w[4] = {v.x, v.y, v.z, v.w};
                    int base = L - 3;
                    #pragma unroll
                    for (int t = 0; t < 4; t++) {
                        int d = pc - (base + t);
                        if (w[t] != 0.0f) don = min(don, d); else doff = min(doff, d);
                    }
                    L -= 4;
                } else {
                    float4 v = rowp[R >> 2];
                    float w[4] = {v.x, v.y, v.z, v.w};
                    #pragma unroll
                    for (int t = 0; t < 4; t++) {
                        int d = (R + t) - pc;
                        if (w[t] != 0.0f) don = min(don, d); else doff = min(doff, d);
                    }
                    R += 4;
                }
            }
            int dr2 = off * off;
            von  = dr2 + don * don;      // exact in int
            voff = dr2 + doff * doff;
        }

        // Group min over the 8 row-slots.
        #pragma unroll
        for (int o = 4; o > 0; o >>= 1) {
            von  = min(von,  __shfl_xor_sync(gmask, von,  o));
            voff = min(voff, __shfl_xor_sync(gmask, voff, o));
        }
        best_on  = min(best_on,  von);
        best_off = min(best_off, voff);

        // Certificate: every unscanned in-range row has |dr| >= 4(j+1).
        int nb  = 4 * (j + 1);
        int nb2 = nb * nb;
        if (best_on <= nb2 && best_off <= nb2) break;
        // Exhaustion: all remaining rows out of range on both sides.
        if ((pr + nb > HH - 1) && (pr - nb - 3 < 0)) break;
    }

    __shared__ int s_on[NPTS];
    __shared__ int s_off[NPTS];
    if (rl == 0) { s_on[n] = best_on; s_off[n] = best_off; }
    __syncthreads();

    // ---- Loss + mean (threads 0..127, neighbor values already in regs) ----
    __shared__ float s_sum[NPTS];
    if (tid < NPTS) {
        int px = pred[2 * tid];
        int py = pred[2 * tid + 1];
        bool outside_frame = (px < 0) || (px > HH) || (py < 0) || (py > WW);
        float loss = 0.0f;
        if (!outside_frame) {
            bool road = (nv0 == 1.0f) || (nv1 == 1.0f) ||
                        (nv2 == 1.0f) || (nv3 == 1.0f);
            const float K1 = 21.7f;
            const float LN2_OVER_K2 = 0.69314718055994531f / 40.0f;
            loss = road ? expf(sqrtf((float)s_off[tid]) * LN2_OVER_K2)
                        : expf(-(float)s_on[tid] / K1);
        }
        s_sum[tid] = loss;
    }
    __syncthreads();
    if (tid < 64) s_sum[tid] += s_sum[tid + 64];
    __syncthreads();
    if (tid < 32) {
        float v = s_sum[tid] + s_sum[tid + 32];
        #pragma unroll
        for (int o = 16; o > 0; o >>= 1)
            v += __shfl_xor_sync(0xFFFFFFFFu, v, o);
        if (tid == 0) out[0] = v * (1.0f / (float)NPTS);
    }
}

extern "C" void kernel_launch(void* const* d_in, const int* in_sizes, int n_in,
                              void* d_out, int out_size) {
    const float* hd  = (const float*)d_in[0];
    const int* pred  = (const int*)d_in[1];
    float* out       = (float*)d_out;
    roadloss_kernel<<<1, 1024>>>(hd, pred, out);
}